// round 7
// baseline (speedup 1.0000x reference)
#include <cuda_runtime.h>
#include <math_constants.h>

#define NSEG 128
#define P    512
#define D    64
#define KT   15
#define NC   8
#define CPS  4                 // CTAs per segment
#define TPB  256
#define NWB  (TPB/32)

__device__ float g_sdist[NSEG * P];
__device__ float g_partials[NSEG];
__device__ int   g_seg_ticket[NSEG];   // zero-init; reset by finisher
__device__ int   g_ticket2 = 0;        // reset by last finisher

__global__ __launch_bounds__(TPB)
void lmnn_kernel(const float* __restrict__ center,
                 const float* __restrict__ outputs,
                 const int*   __restrict__ labels,
                 float*       __restrict__ out)
{
    __shared__ float sdist[P];
    __shared__ int   slab[P];
    __shared__ short sidx[NC][16];
    __shared__ int   sCnt[NC];
    __shared__ int   sTaken[NC];
    __shared__ float sS[NC];
    __shared__ float sM[NC];
    __shared__ float sred[NWB];
    __shared__ int   s_go, s_final;

    const int bid     = blockIdx.x;
    const int seg     = bid >> 2;
    const int quarter = bid & 3;
    const int t       = threadIdx.x;
    const int w       = t >> 5;
    const int lane    = t & 31;

    // ---- Phase 1 loads FIRST: contiguous 32KB quarter, fully coalesced ----
    // float4 index within segment: quarter*2048 + t + 256*s  (s < 8).
    // (t & 15) is the d-offset (constant across s) since 256 % 16 == 0.
    const float4* __restrict__ out4 =
        (const float4*)(outputs + (size_t)seg * P * D) + quarter * 2048;
    float4 v[8];
    #pragma unroll
    for (int s = 0; s < 8; ++s)
        v[s] = __ldg(&out4[t + TPB * s]);
    const float4 c4 = __ldg(&((const float4*)(center + seg * D))[t & 15]);

    // ---- Label-only class scan, overlapped with the load flight. ----
    // All 8 warps participate (warp w = class w). Every CTA does this
    // redundantly so the finisher has it ready.
    // Key: top_k over -dd has all finite entries equal (dist broadcast
    // along k), so jax tie-breaking selects the FIRST KT same-class indices.
    {
        int lab[16];
        #pragma unroll
        for (int u = 0; u < 16; ++u)
            lab[u] = __ldg(&labels[seg * P + u * 32 + lane]);
        if (w == 0) {
            #pragma unroll
            for (int u = 0; u < 16; ++u)
                slab[u * 32 + lane] = lab[u];
        }
        int cnt = 0, taken = 0;
        #pragma unroll
        for (int u = 0; u < 16; ++u) {
            const bool m = (lab[u] == w);
            const unsigned mask = __ballot_sync(0xffffffffu, m);
            const int pc = __popc(mask);
            const int need = KT - taken;
            if (need > 0) {
                const int rank = __popc(mask & ((1u << lane) - 1u));
                if (m && rank < need)
                    sidx[w][taken + rank] = (short)(u * 32 + lane);
                taken += (pc < need) ? pc : need;
            }
            cnt += pc;
        }
        if (lane == 0) { sCnt[w] = cnt; sTaken[w] = taken; }
    }

    // ---- distance compute: 16 lanes = one point; write to global scratch ----
    #pragma unroll
    for (int s = 0; s < 8; ++s) {
        const int gl = quarter * 2048 + t + TPB * s;   // float4 idx in segment
        const float dx = v[s].x - c4.x;
        const float dy = v[s].y - c4.y;
        const float dz = v[s].z - c4.z;
        const float dw = v[s].w - c4.w;
        float part = dx * dx + dy * dy + dz * dz + dw * dw;
        part += __shfl_down_sync(0xffffffffu, part, 8);
        part += __shfl_down_sync(0xffffffffu, part, 4);
        part += __shfl_down_sync(0xffffffffu, part, 2);
        part += __shfl_down_sync(0xffffffffu, part, 1);
        if ((t & 15) == 0)
            g_sdist[seg * P + (gl >> 4)] = part;
    }

    // ---- release scratch writes, take per-segment ticket ----
    __threadfence();
    __syncthreads();
    if (t == 0) {
        const int prev = atomicAdd(&g_seg_ticket[seg], 1);
        s_go = (prev == CPS - 1) ? 1 : 0;
    }
    __syncthreads();
    if (!s_go) return;
    __threadfence();   // acquire sibling CTAs' scratch writes

    // ================== FINISHER (one CTA per segment) ==================
    sdist[t]       = g_sdist[seg * P + t];
    sdist[t + 256] = g_sdist[seg * P + t + 256];
    __syncthreads();

    // ---- gather first-KT distances per class ----
    {
        const int cnt   = sCnt[w];
        const int taken = sTaken[w];
        float d = (lane < KT)
                    ? ((lane < taken) ? sdist[sidx[w][lane]] : CUDART_INF_F)
                    : 0.0f;
        float S  = (lane < KT) ? d : 0.0f;
        float Mx = (lane < KT) ? d : -CUDART_INF_F;
        #pragma unroll
        for (int off = 16; off > 0; off >>= 1) {
            S += __shfl_xor_sync(0xffffffffu, S, off);
            Mx = fmaxf(Mx, __shfl_xor_sync(0xffffffffu, Mx, off));
        }
        if (lane == 0) {
            sS[w] = (cnt > 0) ? S : 0.0f;
            sM[w] = (cnt > 0) ? Mx : -CUDART_INF_F;
        }
    }
    __syncthreads();

    // ---- margin_seg = 1 + max over present classes ----
    float ms = -CUDART_INF_F;
    #pragma unroll
    for (int c = 0; c < NC; ++c)
        ms = fmaxf(ms, sM[c]);
    ms += 1.0f;

    // ---- push term: threads handle points t and t+256 ----
    float term = 0.0f;
    #pragma unroll
    for (int rep = 0; rep < 2; ++rep) {
        const int   j  = t + rep * 256;
        const int   cj = slab[j];
        const float dv = sdist[j];
        if (dv < ms)
            term += (float)(P - sCnt[cj]) * fmaxf(1.0f + sM[cj] - dv, 0.0f);
    }
    #pragma unroll
    for (int off = 16; off > 0; off >>= 1)
        term += __shfl_xor_sync(0xffffffffu, term, off);
    if (lane == 0) sred[w] = term;
    __syncthreads();

    // ---- per-segment total; last finisher reduces all segments ----
    if (t == 0) {
        float push = 0.0f;
        #pragma unroll
        for (int k = 0; k < NWB; ++k) push += sred[k];
        float pull = 0.0f;
        #pragma unroll
        for (int c = 0; c < NC; ++c)
            pull += (float)sCnt[c] * sS[c];
        g_partials[seg] = pull + push;
        g_seg_ticket[seg] = 0;            // reset for next graph replay
        __threadfence();
        const int prev2 = atomicAdd(&g_ticket2, 1);
        s_final = (prev2 == NSEG - 1) ? 1 : 0;
    }
    __syncthreads();

    if (s_final && w == 0) {
        __threadfence();
        const float a  = g_partials[lane];
        const float b  = g_partials[lane + 32];
        const float c2 = g_partials[lane + 64];
        const float d2 = g_partials[lane + 96];
        float vsum = (a + b) + (c2 + d2);
        #pragma unroll
        for (int off = 16; off > 0; off >>= 1)
            vsum += __shfl_xor_sync(0xffffffffu, vsum, off);
        if (lane == 0) {
            out[0] = vsum * (1.0f / (float)(NSEG * P));
            g_ticket2 = 0;                // reset for next graph replay
        }
    }
}

extern "C" void kernel_launch(void* const* d_in, const int* in_sizes, int n_in,
                              void* d_out, int out_size)
{
    const float* center  = (const float*)d_in[0];  // (128, 64)    f32
    const float* outputs = (const float*)d_in[1];  // (128,512,64) f32
    const int*   labels  = (const int*)d_in[2];    // (128, 512)   i32

    lmnn_kernel<<<NSEG * CPS, TPB>>>(center, outputs, labels, (float*)d_out);
}